// round 2
// baseline (speedup 1.0000x reference)
#include <cuda_runtime.h>
#include <math.h>

#define NB   4
#define SQ   2048
#define SKV  4096
#define EDIM 1024
#define CDIM 512
#define HEADS 16
#define HDIM  64

// Scratch (static device arrays: allowed; no allocation)
__device__ float g_cond[(size_t)NB * SQ * EDIM];     // 32 MB: condition @ Wc^T + bc
__device__ float g_attout[(size_t)NB * SKV * EDIM];  // 64 MB: attention output

// ---------------------------------------------------------------------------
// GEMM: C[m][n] = sum_k A[m][k] * W[n][k] + bias[n]
// A: (M,K) row-major, W: (N,K) row-major. M%128==0, N%128==0, K%8==0 assumed.
// 128x128 tile, BK=8, 256 threads, 8x8 per thread.
// ---------------------------------------------------------------------------
__global__ __launch_bounds__(256) void gemm_abt(
    const float* __restrict__ A, const float* __restrict__ W,
    const float* __restrict__ bias, float* __restrict__ C,
    int M, int N, int K)
{
    const int BM = 128, BN = 128, BK = 8;
    __shared__ float As[BK][BM];
    __shared__ float Ws[BK][BN];

    const int tid = threadIdx.x;
    const int mBase = blockIdx.y * BM;
    const int nBase = blockIdx.x * BN;

    const int loadRow = tid >> 1;        // 0..127
    const int loadCol = (tid & 1) * 4;   // 0 or 4

    const int tr = tid >> 4;             // 0..15 (row group)
    const int tc = tid & 15;             // 0..15 (col group)

    float acc[8][8];
    #pragma unroll
    for (int i = 0; i < 8; i++)
        #pragma unroll
        for (int j = 0; j < 8; j++) acc[i][j] = 0.f;

    const float* Aptr = A + (size_t)(mBase + loadRow) * K + loadCol;
    const float* Wptr = W + (size_t)(nBase + loadRow) * K + loadCol;

    for (int k0 = 0; k0 < K; k0 += BK) {
        float4 av = *(const float4*)(Aptr + k0);
        float4 wv = *(const float4*)(Wptr + k0);
        As[loadCol + 0][loadRow] = av.x;
        As[loadCol + 1][loadRow] = av.y;
        As[loadCol + 2][loadRow] = av.z;
        As[loadCol + 3][loadRow] = av.w;
        Ws[loadCol + 0][loadRow] = wv.x;
        Ws[loadCol + 1][loadRow] = wv.y;
        Ws[loadCol + 2][loadRow] = wv.z;
        Ws[loadCol + 3][loadRow] = wv.w;
        __syncthreads();

        #pragma unroll
        for (int k = 0; k < BK; ++k) {
            float rm[8], rn[8];
            *(float4*)&rm[0] = *(const float4*)&As[k][tr * 8];
            *(float4*)&rm[4] = *(const float4*)&As[k][tr * 8 + 4];
            *(float4*)&rn[0] = *(const float4*)&Ws[k][tc * 8];
            *(float4*)&rn[4] = *(const float4*)&Ws[k][tc * 8 + 4];
            #pragma unroll
            for (int i = 0; i < 8; i++)
                #pragma unroll
                for (int j = 0; j < 8; j++)
                    acc[i][j] += rm[i] * rn[j];
        }
        __syncthreads();
    }

    // Epilogue: add bias, store as float4
    #pragma unroll
    for (int i = 0; i < 8; i++) {
        const int m = mBase + tr * 8 + i;
        float* Crow = C + (size_t)m * N + nBase + tc * 8;
        #pragma unroll
        for (int j = 0; j < 8; j += 4) {
            float4 o;
            o.x = acc[i][j + 0] + bias[nBase + tc * 8 + j + 0];
            o.y = acc[i][j + 1] + bias[nBase + tc * 8 + j + 1];
            o.z = acc[i][j + 2] + bias[nBase + tc * 8 + j + 2];
            o.w = acc[i][j + 3] + bias[nBase + tc * 8 + j + 3];
            *(float4*)(Crow + j) = o;
        }
    }
}

// ---------------------------------------------------------------------------
// Per-position heads-attention. One block (256 threads) per (n, t),
// pos = n*SKV + t, 16384 blocks total.
//   cq row: t even -> queries[n, t/2], t odd -> g_cond[n, (t-1)/2]
//   att[h][e] = (1/8) * dot64(cq[h], k[e]); masked; softmax over e; out = att @ v
// ---------------------------------------------------------------------------
__global__ __launch_bounds__(256) void attn_kernel(
    const float* __restrict__ queries, const float* __restrict__ keys,
    const float* __restrict__ values, const int* __restrict__ mask)
{
    __shared__ float cq[1024];
    __shared__ float kT[64 * 17];   // transposed K row with pad: kT[d*17 + e]
    __shared__ float vv[1024];
    __shared__ float sc[16][16];

    const int pos = blockIdx.x;          // 0..16383
    const int n = pos >> 12;             // / SKV
    const int t = pos & (SKV - 1);
    const int tid = threadIdx.x;

    const float* cqrow = (t & 1)
        ? (g_cond  + (size_t)(n * SQ + (t >> 1)) * EDIM)
        : (queries + (size_t)(n * SQ + (t >> 1)) * EDIM);
    const float* krow = keys   + (size_t)pos * EDIM;
    const float* vrow = values + (size_t)pos * EDIM;

    // Coalesced loads: 256 threads x float4 = 1024 floats each
    ((float4*)cq)[tid] = ((const float4*)cqrow)[tid];
    ((float4*)vv)[tid] = ((const float4*)vrow)[tid];
    {
        float4 kv = ((const float4*)krow)[tid];
        int g = tid * 4;                 // element index: e = g>>6, d = g&63
        #pragma unroll
        for (int i = 0; i < 4; i++) {
            int gg = g + i;
            kT[(gg & 63) * 17 + (gg >> 6)] = (&kv.x)[i];
        }
    }
    __syncthreads();

    // Scores: thread (h = tid>>4, e = tid&15)
    const int h = tid >> 4;
    const int e = tid & 15;
    float s = 0.f;
    #pragma unroll
    for (int d = 0; d < HDIM; d++)
        s += cq[h * HDIM + d] * kT[d * 17 + e];
    s *= 0.125f;  // 1/sqrt(64)

    const int mv = mask[(size_t)pos * (HEADS * HEADS) + h * 16 + e];
    if (mv == 0) s = -1e20f;
    sc[h][e] = s;
    __syncthreads();

    // Row softmax (each thread redundantly reduces its 16-wide row)
    float mx = -INFINITY;
    #pragma unroll
    for (int j = 0; j < 16; j++) mx = fmaxf(mx, sc[h][j]);
    float denom = 0.f;
    #pragma unroll
    for (int j = 0; j < 16; j++) denom += expf(sc[h][j] - mx);
    float p = expf(s - mx) / denom;
    __syncthreads();
    sc[h][e] = p;
    __syncthreads();

    // out[h][d] = sum_e p[h][e] * v[e][d]; thread -> 4 consecutive outputs
    const int obase = tid * 4;
    const int oh = obase >> 6;           // head of this output group
    const int od = obase & 63;
    float a0 = 0.f, a1 = 0.f, a2 = 0.f, a3 = 0.f;
    #pragma unroll
    for (int j = 0; j < 16; j++) {
        float a = sc[oh][j];
        const float* vj = vv + j * HDIM + od;
        a0 += a * vj[0];
        a1 += a * vj[1];
        a2 += a * vj[2];
        a3 += a * vj[3];
    }
    float4 o = make_float4(a0, a1, a2, a3);
    ((float4*)(g_attout + (size_t)pos * EDIM))[tid] = o;
}

// ---------------------------------------------------------------------------
// Launch
// ---------------------------------------------------------------------------
extern "C" void kernel_launch(void* const* d_in, const int* in_sizes, int n_in,
                              void* d_out, int out_size)
{
    const float* values    = (const float*)d_in[0];
    const float* keys      = (const float*)d_in[1];
    const float* queries   = (const float*)d_in[2];
    const int*   mask      = (const int*)  d_in[3];
    const float* condition = (const float*)d_in[4];
    const float* Wc        = (const float*)d_in[5];
    const float* bc        = (const float*)d_in[6];
    const float* Wo        = (const float*)d_in[7];
    const float* bo        = (const float*)d_in[8];
    float* out = (float*)d_out;

    float* cond_ptr = nullptr;
    float* attout_ptr = nullptr;
    cudaGetSymbolAddress((void**)&cond_ptr, g_cond);
    cudaGetSymbolAddress((void**)&attout_ptr, g_attout);

    // 1) cond = condition @ Wc^T + bc : M=8192, N=1024, K=512
    {
        dim3 grid(EDIM / 128, (NB * SQ) / 128);
        gemm_abt<<<grid, 256>>>(condition, Wc, bc, cond_ptr, NB * SQ, EDIM, CDIM);
    }

    // 2) per-position attention -> g_attout : 16384 blocks
    attn_kernel<<<NB * SKV, 256>>>(queries, keys, values, mask);

    // 3) out = g_attout @ Wo^T + bo : M=16384, N=1024, K=1024
    {
        dim3 grid(EDIM / 128, (NB * SKV) / 128);
        gemm_abt<<<grid, 256>>>(attout_ptr, Wo, bo, out, NB * SKV, EDIM, EDIM);
    }
}

// round 4
// speedup vs baseline: 2.1773x; 2.1773x over previous
#include <cuda_runtime.h>
#include <cuda_bf16.h>
#include <stdint.h>
#include <math.h>

#define NBATCH 4
#define SQ    2048
#define SKV   4096
#define EDIM  1024
#define CDIM  512
#define HEADS 16
#define HDIM  64

// ---------------------------------------------------------------------------
// Static device scratch (no allocation allowed)
// A_ext layout (M, 3K): [hi | hi | lo];  W_ext layout (N, 3K): [hi | lo | hi]
// => A_ext . W_ext^T = A0B0 + A0B1 + A1B0  (Markidis split, err ~2^-18)
// ---------------------------------------------------------------------------
__device__ float         g_cond[(size_t)NBATCH * SQ * EDIM];           // fp32 cond
__device__ __nv_bfloat16 g_condext[(size_t)NBATCH * SQ * 3 * CDIM];    // 25 MB
__device__ __nv_bfloat16 g_wcext[(size_t)EDIM * 3 * CDIM];             // 3 MB
__device__ __nv_bfloat16 g_woext[(size_t)EDIM * 3 * EDIM];             // 6 MB
__device__ __nv_bfloat16 g_aoext[(size_t)NBATCH * SKV * 3 * EDIM];     // 100 MB

// ---------------------------------------------------------------------------
// PTX helpers (base-target safe: cp.async + ldmatrix + mma.sync only)
// ---------------------------------------------------------------------------
__device__ __forceinline__ uint32_t smem_u32(const void* p) {
    uint32_t a;
    asm("{ .reg .u64 t; cvta.to.shared.u64 t, %1; cvt.u32.u64 %0, t; }"
        : "=r"(a) : "l"(p));
    return a;
}

__device__ __forceinline__ void cp16(uint32_t dst, const void* src) {
    asm volatile("cp.async.cg.shared.global [%0], [%1], 16;\n" :: "r"(dst), "l"(src));
}

#define LDSM4(r, addr) \
    asm volatile("ldmatrix.sync.aligned.m8n8.x4.shared.b16 {%0,%1,%2,%3}, [%4];" \
        : "=r"((r)[0]), "=r"((r)[1]), "=r"((r)[2]), "=r"((r)[3]) : "r"(addr))

#define MMA16816(d, a, b) \
    asm volatile("mma.sync.aligned.m16n8k16.row.col.f32.bf16.bf16.f32 " \
        "{%0,%1,%2,%3}, {%4,%5,%6,%7}, {%8,%9}, {%0,%1,%2,%3};" \
        : "+f"((d)[0]), "+f"((d)[1]), "+f"((d)[2]), "+f"((d)[3]) \
        : "r"((a)[0]), "r"((a)[1]), "r"((a)[2]), "r"((a)[3]), \
          "r"((b)[0]), "r"((b)[1]))

// ---------------------------------------------------------------------------
// split+pack: fp32 (M,K) -> bf16 (M,3K).
// act mode: [hi | hi | lo]; weight mode: [hi | lo | hi].
// ---------------------------------------------------------------------------
__global__ __launch_bounds__(256) void split_pack(
    const float* __restrict__ src, __nv_bfloat16* __restrict__ dst,
    int K, int act, int n)
{
    int i = (blockIdx.x * blockDim.x + threadIdx.x) * 4;
    if (i >= n) return;
    int m = i / K, k = i % K;
    float4 v = *(const float4*)(src + i);
    float x[4] = {v.x, v.y, v.z, v.w};
    __nv_bfloat16 hi[4], lo[4];
    #pragma unroll
    for (int j = 0; j < 4; j++) {
        hi[j] = __float2bfloat16_rn(x[j]);
        lo[j] = __float2bfloat16_rn(x[j] - __bfloat162float(hi[j]));
    }
    size_t base = (size_t)m * 3 * K + k;
    uint2 hw = *(uint2*)hi;
    uint2 lw = *(uint2*)lo;
    *(uint2*)(dst + base) = hw;
    if (act) {
        *(uint2*)(dst + base + K)     = hw;
        *(uint2*)(dst + base + 2 * K) = lw;
    } else {
        *(uint2*)(dst + base + K)     = lw;
        *(uint2*)(dst + base + 2 * K) = hw;
    }
}

// ---------------------------------------------------------------------------
// HMMA GEMM: C[m][n] = sum_k A[m][k]*B[n][k] + bias[n]
// A (M,K3) bf16 row-major, B (N,K3) bf16 row-major, C fp32.
// BM=BN=128, BK=32, 8 warps (warp tile 32x64), 4-stage cp.async pipeline.
// SMEM rows padded to 80B (20-word stride => conflict-free ldmatrix).
// ---------------------------------------------------------------------------
#define BM 128
#define BN 128
#define BKC 32
#define AROW 80
#define ASTAGE (128 * AROW)       // 10240 B
#define STAGE  (2 * ASTAGE)       // 20480 B
#define NSTAGE 4
#define DSMEM  (NSTAGE * STAGE)   // 81920 B

__device__ __forceinline__ void gemm_issue(
    uint32_t s0, int slot, int k0, int tid, int mBase, int nBase,
    const __nv_bfloat16* __restrict__ A, const __nv_bfloat16* __restrict__ B,
    int K3)
{
    uint32_t sA = s0 + slot * STAGE;
    uint32_t sB = sA + ASTAGE;
    #pragma unroll
    for (int i = 0; i < 2; i++) {
        int ch = tid + i * 256;
        int r = ch >> 2, c = ch & 3;
        cp16(sA + r * AROW + c * 16, A + (size_t)(mBase + r) * K3 + k0 + c * 8);
        cp16(sB + r * AROW + c * 16, B + (size_t)(nBase + r) * K3 + k0 + c * 8);
    }
    asm volatile("cp.async.commit_group;");
}

__global__ __launch_bounds__(256) void gemm_hmma(
    const __nv_bfloat16* __restrict__ A, const __nv_bfloat16* __restrict__ B,
    const float* __restrict__ bias, float* __restrict__ C,
    int M, int N, int K3)
{
    extern __shared__ char smem[];
    const int tid  = threadIdx.x;
    const int wid  = tid >> 5;
    const int lane = tid & 31;
    const int mBase = blockIdx.y * BM;
    const int nBase = blockIdx.x * BN;
    const int wm = (wid & 3) * 32;   // warp M offset in tile
    const int wn = (wid >> 2) * 64;  // warp N offset in tile

    const uint32_t s0 = smem_u32(smem);

    float acc[2][8][4];
    #pragma unroll
    for (int i = 0; i < 2; i++)
        #pragma unroll
        for (int j = 0; j < 8; j++)
            #pragma unroll
            for (int q = 0; q < 4; q++) acc[i][j][q] = 0.f;

    const int NC = K3 / BKC;

    // prefetch 3 stages
    gemm_issue(s0, 0, 0, tid, mBase, nBase, A, B, K3);
    gemm_issue(s0, 1, BKC, tid, mBase, nBase, A, B, K3);
    gemm_issue(s0, 2, 2 * BKC, tid, mBase, nBase, A, B, K3);

    for (int c = 0; c < NC; c++) {
        asm volatile("cp.async.wait_group 2;");
        __syncthreads();

        if (c + 3 < NC)
            gemm_issue(s0, (c + 3) & 3, (c + 3) * BKC, tid, mBase, nBase, A, B, K3);
        else
            asm volatile("cp.async.commit_group;");

        uint32_t sA = s0 + (c & 3) * STAGE;
        uint32_t sB = sA + ASTAGE;

        #pragma unroll
        for (int ks = 0; ks < 2; ks++) {
            uint32_t a_frag[2][4];
            uint32_t b_frag[8][2];
            #pragma unroll
            for (int mi = 0; mi < 2; mi++) {
                uint32_t addr = sA + (wm + mi * 16 + (lane & 15)) * AROW
                              + ks * 32 + (lane >> 4) * 16;
                LDSM4(a_frag[mi], addr);
            }
            #pragma unroll
            for (int p = 0; p < 4; p++) {
                int grp = lane >> 3, w = lane & 7;
                int nsel = p * 2 + (grp >> 1);
                uint32_t addr = sB + (wn + nsel * 8 + w) * AROW
                              + ks * 32 + (grp & 1) * 16;
                uint32_t r[4];
                LDSM4(r, addr);
                b_frag[p * 2][0]     = r[0];
                b_frag[p * 2][1]     = r[1];
                b_frag[p * 2 + 1][0] = r[2];
                b_frag[p * 2 + 1][1] = r[3];
            }
            #pragma unroll
            for (int mi = 0; mi < 2; mi++)
                #pragma unroll
                for (int ni = 0; ni < 8; ni++)
                    MMA16816(acc[mi][ni], a_frag[mi], b_frag[ni]);
        }
    }

    // epilogue: lane holds rows g,g+8 / cols tg*2,tg*2+1 of each (mi,ni) frag
    const int g = lane >> 2, tg = lane & 3;
    #pragma unroll
    for (int mi = 0; mi < 2; mi++) {
        int row0 = mBase + wm + mi * 16 + g;
        #pragma unroll
        for (int ni = 0; ni < 8; ni++) {
            int col = nBase + wn + ni * 8 + tg * 2;
            float b0 = bias[col], b1 = bias[col + 1];
            float2 v0 = make_float2(acc[mi][ni][0] + b0, acc[mi][ni][1] + b1);
            float2 v1 = make_float2(acc[mi][ni][2] + b0, acc[mi][ni][3] + b1);
            *(float2*)(C + (size_t)row0 * N + col) = v0;
            *(float2*)(C + (size_t)(row0 + 8) * N + col) = v1;
        }
    }
}

// ---------------------------------------------------------------------------
// Per-position heads-attention (fp32 exact). Writes packed bf16 [hi|hi|lo].
// ---------------------------------------------------------------------------
__global__ __launch_bounds__(256) void attn_kernel(
    const float* __restrict__ queries, const float* __restrict__ keys,
    const float* __restrict__ values, const int* __restrict__ mask)
{
    __shared__ float cq[1024];
    __shared__ float kT[64 * 17];
    __shared__ float vv[1024];
    __shared__ float sc[16][16];

    const int pos = blockIdx.x;
    const int n = pos >> 12;
    const int t = pos & (SKV - 1);
    const int tid = threadIdx.x;

    const float* cqrow = (t & 1)
        ? (g_cond  + (size_t)(n * SQ + (t >> 1)) * EDIM)
        : (queries + (size_t)(n * SQ + (t >> 1)) * EDIM);
    const float* krow = keys   + (size_t)pos * EDIM;
    const float* vrow = values + (size_t)pos * EDIM;

    ((float4*)cq)[tid] = ((const float4*)cqrow)[tid];
    ((float4*)vv)[tid] = ((const float4*)vrow)[tid];
    {
        float4 kv = ((const float4*)krow)[tid];
        int gidx = tid * 4;
        #pragma unroll
        for (int i = 0; i < 4; i++) {
            int gg = gidx + i;
            kT[(gg & 63) * 17 + (gg >> 6)] = (&kv.x)[i];
        }
    }
    __syncthreads();

    const int h = tid >> 4;
    const int e = tid & 15;
    float s = 0.f;
    #pragma unroll
    for (int d = 0; d < HDIM; d++)
        s += cq[h * HDIM + d] * kT[d * 17 + e];
    s *= 0.125f;

    if (mask[(size_t)pos * (HEADS * HEADS) + h * 16 + e] == 0) s = -1e20f;
    sc[h][e] = s;
    __syncthreads();

    float mx = -INFINITY;
    #pragma unroll
    for (int j = 0; j < 16; j++) mx = fmaxf(mx, sc[h][j]);
    float denom = 0.f;
    #pragma unroll
    for (int j = 0; j < 16; j++) denom += expf(sc[h][j] - mx);
    float p = expf(s - mx) / denom;
    __syncthreads();
    sc[h][e] = p;
    __syncthreads();

    const int obase = tid * 4;
    const int oh = obase >> 6;
    const int od = obase & 63;
    float a0 = 0.f, a1 = 0.f, a2 = 0.f, a3 = 0.f;
    #pragma unroll
    for (int j = 0; j < 16; j++) {
        float a = sc[oh][j];
        const float* vj = vv + j * HDIM + od;
        a0 += a * vj[0];
        a1 += a * vj[1];
        a2 += a * vj[2];
        a3 += a * vj[3];
    }

    float o[4] = {a0, a1, a2, a3};
    __nv_bfloat16 hi[4], lo[4];
    #pragma unroll
    for (int j = 0; j < 4; j++) {
        hi[j] = __float2bfloat16_rn(o[j]);
        lo[j] = __float2bfloat16_rn(o[j] - __bfloat162float(hi[j]));
    }
    size_t base = (size_t)pos * (3 * EDIM) + obase;
    uint2 hw = *(uint2*)hi;
    uint2 lw = *(uint2*)lo;
    *(uint2*)(g_aoext + base)            = hw;
    *(uint2*)(g_aoext + base + EDIM)     = hw;
    *(uint2*)(g_aoext + base + 2 * EDIM) = lw;
}

// ---------------------------------------------------------------------------
// Launch
// ---------------------------------------------------------------------------
extern "C" void kernel_launch(void* const* d_in, const int* in_sizes, int n_in,
                              void* d_out, int out_size)
{
    const float* values    = (const float*)d_in[0];
    const float* keys      = (const float*)d_in[1];
    const float* queries   = (const float*)d_in[2];
    const int*   mask      = (const int*)  d_in[3];
    const float* condition = (const float*)d_in[4];
    const float* Wc        = (const float*)d_in[5];
    const float* bc        = (const float*)d_in[6];
    const float* Wo        = (const float*)d_in[7];
    const float* bo        = (const float*)d_in[8];
    float* out = (float*)d_out;

    float* cond_ptr;
    __nv_bfloat16 *cext, *wcext, *woext, *aoext;
    cudaGetSymbolAddress((void**)&cond_ptr, g_cond);
    cudaGetSymbolAddress((void**)&cext,  g_condext);
    cudaGetSymbolAddress((void**)&wcext, g_wcext);
    cudaGetSymbolAddress((void**)&woext, g_woext);
    cudaGetSymbolAddress((void**)&aoext, g_aoext);

    cudaFuncSetAttribute(gemm_hmma,
                         cudaFuncAttributeMaxDynamicSharedMemorySize, DSMEM);

    // splits / packs
    {
        int n = NBATCH * SQ * CDIM;   // condition activations
        split_pack<<<n / 4 / 256, 256>>>(condition, cext, CDIM, 1, n);
        n = EDIM * CDIM;              // Wc
        split_pack<<<n / 4 / 256, 256>>>(Wc, wcext, CDIM, 0, n);
        n = EDIM * EDIM;              // Wo
        split_pack<<<n / 4 / 256, 256>>>(Wo, woext, EDIM, 0, n);
    }

    // 1) cond = condition @ Wc^T + bc : M=8192, N=1024, K3=1536
    {
        dim3 grid(EDIM / BN, (NBATCH * SQ) / BM);
        gemm_hmma<<<grid, 256, DSMEM>>>(cext, wcext, bc, cond_ptr,
                                        NBATCH * SQ, EDIM, 3 * CDIM);
    }

    // 2) attention -> g_aoext (packed bf16 split)
    attn_kernel<<<NBATCH * SKV, 256>>>(queries, keys, values, mask);

    // 3) out = attout @ Wo^T + bo : M=16384, N=1024, K3=3072
    {
        dim3 grid(EDIM / BN, (NBATCH * SKV) / BM);
        gemm_hmma<<<grid, 256, DSMEM>>>(aoext, woext, bo, out,
                                        NBATCH * SKV, EDIM, 3 * EDIM);
    }
}

// round 5
// speedup vs baseline: 2.2447x; 1.0310x over previous
#include <cuda_runtime.h>
#include <cuda_bf16.h>
#include <stdint.h>
#include <math.h>

#define NBATCH 4
#define SQ    2048
#define SKV   4096
#define EDIM  1024
#define CDIM  512
#define HEADS 16
#define HDIM  64

// ---------------------------------------------------------------------------
// Static device scratch. All split operands stored [hi | lo] (width 2K).
// Logical GEMM runs K3=3K with per-chunk source remap:
//   A terms: hi, hi, lo     B terms: hi, lo, hi
// => sum = A0B0 + A0B1 + A1B0  (Markidis split, err ~2^-18)
// ---------------------------------------------------------------------------
__device__ float         g_cond[(size_t)NBATCH * SQ * EDIM];           // fp32 cond
__device__ __nv_bfloat16 g_condext[(size_t)NBATCH * SQ * 2 * CDIM];    // 16 MB
__device__ __nv_bfloat16 g_wcext[(size_t)EDIM * 2 * CDIM];             // 2 MB
__device__ __nv_bfloat16 g_woext[(size_t)EDIM * 2 * EDIM];             // 4 MB
__device__ __nv_bfloat16 g_aoext[(size_t)NBATCH * SKV * 2 * EDIM];     // 67 MB

// ---------------------------------------------------------------------------
// PTX helpers (base-target safe: cp.async + ldmatrix + mma.sync only)
// ---------------------------------------------------------------------------
__device__ __forceinline__ uint32_t smem_u32(const void* p) {
    uint32_t a;
    asm("{ .reg .u64 t; cvta.to.shared.u64 t, %1; cvt.u32.u64 %0, t; }"
        : "=r"(a) : "l"(p));
    return a;
}

__device__ __forceinline__ void cp16(uint32_t dst, const void* src) {
    asm volatile("cp.async.cg.shared.global [%0], [%1], 16;\n" :: "r"(dst), "l"(src));
}

#define LDSM4(r, addr) \
    asm volatile("ldmatrix.sync.aligned.m8n8.x4.shared.b16 {%0,%1,%2,%3}, [%4];" \
        : "=r"((r)[0]), "=r"((r)[1]), "=r"((r)[2]), "=r"((r)[3]) : "r"(addr))

#define MMA16816(d, a, b) \
    asm volatile("mma.sync.aligned.m16n8k16.row.col.f32.bf16.bf16.f32 " \
        "{%0,%1,%2,%3}, {%4,%5,%6,%7}, {%8,%9}, {%0,%1,%2,%3};" \
        : "+f"((d)[0]), "+f"((d)[1]), "+f"((d)[2]), "+f"((d)[3]) \
        : "r"((a)[0]), "r"((a)[1]), "r"((a)[2]), "r"((a)[3]), \
          "r"((b)[0]), "r"((b)[1]))

// ---------------------------------------------------------------------------
// split: fp32 (M,K) -> bf16 (M,2K) as [hi | lo]
// ---------------------------------------------------------------------------
__global__ __launch_bounds__(256) void split_pack(
    const float* __restrict__ src, __nv_bfloat16* __restrict__ dst,
    int K, int n)
{
    int i = (blockIdx.x * blockDim.x + threadIdx.x) * 4;
    if (i >= n) return;
    int m = i / K, k = i % K;
    float4 v = *(const float4*)(src + i);
    float x[4] = {v.x, v.y, v.z, v.w};
    __nv_bfloat16 hi[4], lo[4];
    #pragma unroll
    for (int j = 0; j < 4; j++) {
        hi[j] = __float2bfloat16_rn(x[j]);
        lo[j] = __float2bfloat16_rn(x[j] - __bfloat162float(hi[j]));
    }
    size_t base = (size_t)m * 2 * K + k;
    *(uint2*)(dst + base)     = *(uint2*)hi;
    *(uint2*)(dst + base + K) = *(uint2*)lo;
}

// ---------------------------------------------------------------------------
// HMMA GEMM: C[m][n] = sum over 3K logical k of A_ext*B_ext + bias[n]
// A (M,2K) bf16 [hi|lo], B (N,2K) bf16 [hi|lo]. Chunk source remap gives the
// 3-term product. BM=BN=128, BK=32, 8 warps (32x64 warp tile), 3-stage
// cp.async pipeline (61.4KB smem -> 2 CTAs/SM).
// ---------------------------------------------------------------------------
#define BM 128
#define BN 128
#define BKC 32
#define AROW 80
#define ASTAGE (128 * AROW)       // 10240 B
#define STAGE  (2 * ASTAGE)       // 20480 B
#define NSTAGE 3
#define DSMEM  (NSTAGE * STAGE)   // 61440 B

__device__ __forceinline__ void gemm_issue(
    uint32_t s0, int slot, int c, int nc1, int K, int tid, int mBase, int nBase,
    const __nv_bfloat16* __restrict__ A, const __nv_bfloat16* __restrict__ B)
{
    // term schedule: A: hi,hi,lo   B: hi,lo,hi
    int k0A, k0B;
    if (c < nc1)          { k0A = c * BKC;              k0B = c * BKC; }
    else if (c < 2 * nc1) { k0A = (c - nc1) * BKC;      k0B = K + (c - nc1) * BKC; }
    else                  { k0A = K + (c - 2 * nc1) * BKC; k0B = (c - 2 * nc1) * BKC; }

    const int K2 = 2 * K;
    uint32_t sA = s0 + slot * STAGE;
    uint32_t sB = sA + ASTAGE;
    #pragma unroll
    for (int i = 0; i < 2; i++) {
        int ch = tid + i * 256;
        int r = ch >> 2, col = ch & 3;
        cp16(sA + r * AROW + col * 16, A + (size_t)(mBase + r) * K2 + k0A + col * 8);
        cp16(sB + r * AROW + col * 16, B + (size_t)(nBase + r) * K2 + k0B + col * 8);
    }
    asm volatile("cp.async.commit_group;");
}

__global__ __launch_bounds__(256, 2) void gemm_hmma(
    const __nv_bfloat16* __restrict__ A, const __nv_bfloat16* __restrict__ B,
    const float* __restrict__ bias, float* __restrict__ C,
    int M, int N, int K)
{
    extern __shared__ char smem[];
    const int tid  = threadIdx.x;
    const int wid  = tid >> 5;
    const int lane = tid & 31;
    const int mBase = blockIdx.y * BM;
    const int nBase = blockIdx.x * BN;
    const int wm = (wid & 3) * 32;
    const int wn = (wid >> 2) * 64;

    const uint32_t s0 = smem_u32(smem);
    const int nc1 = K / BKC;
    const int NC = 3 * nc1;

    float acc[2][8][4];
    #pragma unroll
    for (int i = 0; i < 2; i++)
        #pragma unroll
        for (int j = 0; j < 8; j++)
            #pragma unroll
            for (int q = 0; q < 4; q++) acc[i][j][q] = 0.f;

    gemm_issue(s0, 0, 0, nc1, K, tid, mBase, nBase, A, B);
    gemm_issue(s0, 1, 1, nc1, K, tid, mBase, nBase, A, B);

    for (int c = 0; c < NC; c++) {
        asm volatile("cp.async.wait_group 1;");
        __syncthreads();

        if (c + 2 < NC) {
            int slot = (c + 2) % NSTAGE;
            gemm_issue(s0, slot, c + 2, nc1, K, tid, mBase, nBase, A, B);
        } else {
            asm volatile("cp.async.commit_group;");
        }

        uint32_t sA = s0 + (c % NSTAGE) * STAGE;
        uint32_t sB = sA + ASTAGE;

        #pragma unroll
        for (int ks = 0; ks < 2; ks++) {
            uint32_t a_frag[2][4];
            uint32_t b_frag[8][2];
            #pragma unroll
            for (int mi = 0; mi < 2; mi++) {
                uint32_t addr = sA + (wm + mi * 16 + (lane & 15)) * AROW
                              + ks * 32 + (lane >> 4) * 16;
                LDSM4(a_frag[mi], addr);
            }
            #pragma unroll
            for (int p = 0; p < 4; p++) {
                int grp = lane >> 3, w = lane & 7;
                int nsel = p * 2 + (grp >> 1);
                uint32_t addr = sB + (wn + nsel * 8 + w) * AROW
                              + ks * 32 + (grp & 1) * 16;
                uint32_t r[4];
                LDSM4(r, addr);
                b_frag[p * 2][0]     = r[0];
                b_frag[p * 2][1]     = r[1];
                b_frag[p * 2 + 1][0] = r[2];
                b_frag[p * 2 + 1][1] = r[3];
            }
            #pragma unroll
            for (int mi = 0; mi < 2; mi++)
                #pragma unroll
                for (int ni = 0; ni < 8; ni++)
                    MMA16816(acc[mi][ni], a_frag[mi], b_frag[ni]);
        }
    }

    const int g = lane >> 2, tg = lane & 3;
    #pragma unroll
    for (int mi = 0; mi < 2; mi++) {
        int row0 = mBase + wm + mi * 16 + g;
        #pragma unroll
        for (int ni = 0; ni < 8; ni++) {
            int col = nBase + wn + ni * 8 + tg * 2;
            float b0 = __ldg(bias + col), b1 = __ldg(bias + col + 1);
            float2 v0 = make_float2(acc[mi][ni][0] + b0, acc[mi][ni][1] + b1);
            float2 v1 = make_float2(acc[mi][ni][2] + b0, acc[mi][ni][3] + b1);
            *(float2*)(C + (size_t)row0 * N + col) = v0;
            *(float2*)(C + (size_t)(row0 + 8) * N + col) = v1;
        }
    }
}

// ---------------------------------------------------------------------------
// Per-position heads-attention (fp32 exact). Writes bf16 [hi | lo] rows.
// ---------------------------------------------------------------------------
__global__ __launch_bounds__(256) void attn_kernel(
    const float* __restrict__ queries, const float* __restrict__ keys,
    const float* __restrict__ values, const int* __restrict__ mask)
{
    __shared__ float cq[1024];
    __shared__ float kT[64 * 17];
    __shared__ float vv[1024];
    __shared__ float sc[16][16];

    const int pos = blockIdx.x;
    const int n = pos >> 12;
    const int t = pos & (SKV - 1);
    const int tid = threadIdx.x;

    const float* cqrow = (t & 1)
        ? (g_cond  + (size_t)(n * SQ + (t >> 1)) * EDIM)
        : (queries + (size_t)(n * SQ + (t >> 1)) * EDIM);
    const float* krow = keys   + (size_t)pos * EDIM;
    const float* vrow = values + (size_t)pos * EDIM;

    ((float4*)cq)[tid] = ((const float4*)cqrow)[tid];
    ((float4*)vv)[tid] = ((const float4*)vrow)[tid];
    {
        float4 kv = ((const float4*)krow)[tid];
        int gidx = tid * 4;
        #pragma unroll
        for (int i = 0; i < 4; i++) {
            int gg = gidx + i;
            kT[(gg & 63) * 17 + (gg >> 6)] = (&kv.x)[i];
        }
    }
    __syncthreads();

    const int h = tid >> 4;
    const int e = tid & 15;
    float s = 0.f;
    #pragma unroll
    for (int d = 0; d < HDIM; d++)
        s += cq[h * HDIM + d] * kT[d * 17 + e];
    s *= 0.125f;

    if (mask[(size_t)pos * (HEADS * HEADS) + h * 16 + e] == 0) s = -1e20f;
    sc[h][e] = s;
    __syncthreads();

    float mx = -INFINITY;
    #pragma unroll
    for (int j = 0; j < 16; j++) mx = fmaxf(mx, sc[h][j]);
    float denom = 0.f;
    #pragma unroll
    for (int j = 0; j < 16; j++) denom += expf(sc[h][j] - mx);
    float p = expf(s - mx) / denom;
    __syncthreads();
    sc[h][e] = p;
    __syncthreads();

    const int obase = tid * 4;
    const int oh = obase >> 6;
    const int od = obase & 63;
    float a0 = 0.f, a1 = 0.f, a2 = 0.f, a3 = 0.f;
    #pragma unroll
    for (int j = 0; j < 16; j++) {
        float a = sc[oh][j];
        const float* vj = vv + j * HDIM + od;
        a0 += a * vj[0];
        a1 += a * vj[1];
        a2 += a * vj[2];
        a3 += a * vj[3];
    }

    float o[4] = {a0, a1, a2, a3};
    __nv_bfloat16 hi[4], lo[4];
    #pragma unroll
    for (int j = 0; j < 4; j++) {
        hi[j] = __float2bfloat16_rn(o[j]);
        lo[j] = __float2bfloat16_rn(o[j] - __bfloat162float(hi[j]));
    }
    size_t base = (size_t)pos * (2 * EDIM) + obase;
    *(uint2*)(g_aoext + base)        = *(uint2*)hi;
    *(uint2*)(g_aoext + base + EDIM) = *(uint2*)lo;
}

// ---------------------------------------------------------------------------
// Launch
// ---------------------------------------------------------------------------
extern "C" void kernel_launch(void* const* d_in, const int* in_sizes, int n_in,
                              void* d_out, int out_size)
{
    const float* values    = (const float*)d_in[0];
    const float* keys      = (const float*)d_in[1];
    const float* queries   = (const float*)d_in[2];
    const int*   mask      = (const int*)  d_in[3];
    const float* condition = (const float*)d_in[4];
    const float* Wc        = (const float*)d_in[5];
    const float* bc        = (const float*)d_in[6];
    const float* Wo        = (const float*)d_in[7];
    const float* bo        = (const float*)d_in[8];
    float* out = (float*)d_out;

    float* cond_ptr;
    __nv_bfloat16 *cext, *wcext, *woext, *aoext;
    cudaGetSymbolAddress((void**)&cond_ptr, g_cond);
    cudaGetSymbolAddress((void**)&cext,  g_condext);
    cudaGetSymbolAddress((void**)&wcext, g_wcext);
    cudaGetSymbolAddress((void**)&woext, g_woext);
    cudaGetSymbolAddress((void**)&aoext, g_aoext);

    cudaFuncSetAttribute(gemm_hmma,
                         cudaFuncAttributeMaxDynamicSharedMemorySize, DSMEM);

    // splits
    {
        int n = NBATCH * SQ * CDIM;
        split_pack<<<n / 4 / 256, 256>>>(condition, cext, CDIM, n);
        n = EDIM * CDIM;
        split_pack<<<n / 4 / 256, 256>>>(Wc, wcext, CDIM, n);
        n = EDIM * EDIM;
        split_pack<<<n / 4 / 256, 256>>>(Wo, woext, EDIM, n);
    }

    // 1) cond = condition @ Wc^T + bc : M=8192, N=1024, K=512 (K3=1536)
    {
        dim3 grid(EDIM / BN, (NBATCH * SQ) / BM);
        gemm_hmma<<<grid, 256, DSMEM>>>(cext, wcext, bc, cond_ptr,
                                        NBATCH * SQ, EDIM, CDIM);
    }

    // 2) attention -> g_aoext (bf16 [hi|lo])
    attn_kernel<<<NBATCH * SKV, 256>>>(queries, keys, values, mask);

    // 3) out = attout @ Wo^T + bo : M=16384, N=1024, K=1024 (K3=3072)
    {
        dim3 grid(EDIM / BN, (NBATCH * SKV) / BM);
        gemm_hmma<<<grid, 256, DSMEM>>>(aoext, woext, bo, out,
                                        NBATCH * SKV, EDIM, EDIM);
    }
}

// round 6
// speedup vs baseline: 2.5028x; 1.1150x over previous
#include <cuda_runtime.h>
#include <cuda_bf16.h>
#include <stdint.h>
#include <math.h>

#define NBATCH 4
#define SQ    2048
#define SKV   4096
#define EDIM  1024
#define CDIM  512
#define HEADS 16
#define HDIM  64

// ---------------------------------------------------------------------------
// Static device scratch. Split operands stored [hi | lo] (width 2K).
// Logical GEMM runs K3=3K with per-chunk source remap:
//   A terms: hi, hi, lo     B terms: hi, lo, hi
// => sum = A0B0 + A0B1 + A1B0  (Markidis split, err ~2^-18)
// ---------------------------------------------------------------------------
__device__ float         g_cond[(size_t)NBATCH * SQ * EDIM];
__device__ __nv_bfloat16 g_condext[(size_t)NBATCH * SQ * 2 * CDIM];
__device__ __nv_bfloat16 g_wcext[(size_t)EDIM * 2 * CDIM];
__device__ __nv_bfloat16 g_woext[(size_t)EDIM * 2 * EDIM];
__device__ __nv_bfloat16 g_aoext[(size_t)NBATCH * SKV * 2 * EDIM];

// ---------------------------------------------------------------------------
// PTX helpers
// ---------------------------------------------------------------------------
__device__ __forceinline__ uint32_t smem_u32(const void* p) {
    uint32_t a;
    asm("{ .reg .u64 t; cvta.to.shared.u64 t, %1; cvt.u32.u64 %0, t; }"
        : "=r"(a) : "l"(p));
    return a;
}

__device__ __forceinline__ void cp16(uint32_t dst, const void* src) {
    asm volatile("cp.async.cg.shared.global [%0], [%1], 16;\n" :: "r"(dst), "l"(src));
}

#define LDSM4(r, addr) \
    asm volatile("ldmatrix.sync.aligned.m8n8.x4.shared.b16 {%0,%1,%2,%3}, [%4];" \
        : "=r"((r)[0]), "=r"((r)[1]), "=r"((r)[2]), "=r"((r)[3]) : "r"(addr))

#define MMA16816(d, a, b) \
    asm volatile("mma.sync.aligned.m16n8k16.row.col.f32.bf16.bf16.f32 " \
        "{%0,%1,%2,%3}, {%4,%5,%6,%7}, {%8,%9}, {%0,%1,%2,%3};" \
        : "+f"((d)[0]), "+f"((d)[1]), "+f"((d)[2]), "+f"((d)[3]) \
        : "r"((a)[0]), "r"((a)[1]), "r"((a)[2]), "r"((a)[3]), \
          "r"((b)[0]), "r"((b)[1]))

// ---------------------------------------------------------------------------
// split: fp32 (M,K) -> bf16 (M,2K) as [hi | lo]
// ---------------------------------------------------------------------------
__global__ __launch_bounds__(256) void split_pack(
    const float* __restrict__ src, __nv_bfloat16* __restrict__ dst,
    int K, int n)
{
    int i = (blockIdx.x * blockDim.x + threadIdx.x) * 4;
    if (i >= n) return;
    int m = i / K, k = i % K;
    float4 v = *(const float4*)(src + i);
    float x[4] = {v.x, v.y, v.z, v.w};
    __nv_bfloat16 hi[4], lo[4];
    #pragma unroll
    for (int j = 0; j < 4; j++) {
        hi[j] = __float2bfloat16_rn(x[j]);
        lo[j] = __float2bfloat16_rn(x[j] - __bfloat162float(hi[j]));
    }
    size_t base = (size_t)m * 2 * K + k;
    *(uint2*)(dst + base)     = *(uint2*)hi;
    *(uint2*)(dst + base + K) = *(uint2*)lo;
}

// ---------------------------------------------------------------------------
// HMMA GEMM. BM=BN=128, BKC=64, 8 warps (32x64 warp tile), 3-stage cp.async.
// SMEM rows 144B (128B data + 16B pad): row stride 36 words == 4 mod 32,
// ldmatrix phases conflict-free. 110.6KB/CTA -> 2 CTAs/SM.
// ---------------------------------------------------------------------------
#define BM 128
#define BN 128
#define BKC 64
#define AROW 144
#define ASTAGE (128 * AROW)       // 18432 B
#define STAGE  (2 * ASTAGE)       // 36864 B
#define NSTAGE 3
#define DSMEM  (NSTAGE * STAGE)   // 110592 B

__device__ __forceinline__ void gemm_issue(
    uint32_t s0, int slot, int c, int nc1, int K, int tid, int mBase, int nBase,
    const __nv_bfloat16* __restrict__ A, const __nv_bfloat16* __restrict__ B)
{
    // term schedule: A: hi,hi,lo   B: hi,lo,hi
    int k0A, k0B;
    if (c < nc1)          { k0A = c * BKC;                 k0B = c * BKC; }
    else if (c < 2 * nc1) { k0A = (c - nc1) * BKC;         k0B = K + (c - nc1) * BKC; }
    else                  { k0A = K + (c - 2 * nc1) * BKC; k0B = (c - 2 * nc1) * BKC; }

    const int K2 = 2 * K;
    uint32_t sA = s0 + slot * STAGE;
    uint32_t sB = sA + ASTAGE;
    #pragma unroll
    for (int i = 0; i < 4; i++) {
        int ch = tid + i * 256;          // 0..1023
        int r = ch >> 3, col = ch & 7;   // row, 16B-chunk within 128B
        cp16(sA + r * AROW + col * 16, A + (size_t)(mBase + r) * K2 + k0A + col * 8);
        cp16(sB + r * AROW + col * 16, B + (size_t)(nBase + r) * K2 + k0B + col * 8);
    }
    asm volatile("cp.async.commit_group;");
}

__global__ __launch_bounds__(256, 2) void gemm_hmma(
    const __nv_bfloat16* __restrict__ A, const __nv_bfloat16* __restrict__ B,
    const float* __restrict__ bias, float* __restrict__ C,
    int M, int N, int K)
{
    extern __shared__ char smem[];
    const int tid  = threadIdx.x;
    const int wid  = tid >> 5;
    const int lane = tid & 31;
    const int mBase = blockIdx.y * BM;
    const int nBase = blockIdx.x * BN;
    const int wm = (wid & 3) * 32;
    const int wn = (wid >> 2) * 64;

    const uint32_t s0 = smem_u32(smem);
    const int nc1 = K / BKC;
    const int NC = 3 * nc1;

    float acc[2][8][4];
    #pragma unroll
    for (int i = 0; i < 2; i++)
        #pragma unroll
        for (int j = 0; j < 8; j++)
            #pragma unroll
            for (int q = 0; q < 4; q++) acc[i][j][q] = 0.f;

    gemm_issue(s0, 0, 0, nc1, K, tid, mBase, nBase, A, B);
    gemm_issue(s0, 1, 1, nc1, K, tid, mBase, nBase, A, B);

    for (int c = 0; c < NC; c++) {
        asm volatile("cp.async.wait_group 1;");
        __syncthreads();

        if (c + 2 < NC) {
            int slot = (c + 2) % NSTAGE;
            gemm_issue(s0, slot, c + 2, nc1, K, tid, mBase, nBase, A, B);
        } else {
            asm volatile("cp.async.commit_group;");
        }

        uint32_t sA = s0 + (c % NSTAGE) * STAGE;
        uint32_t sB = sA + ASTAGE;

        #pragma unroll
        for (int ks = 0; ks < 4; ks++) {
            uint32_t a_frag[2][4];
            uint32_t b_frag[8][2];
            #pragma unroll
            for (int mi = 0; mi < 2; mi++) {
                uint32_t addr = sA + (wm + mi * 16 + (lane & 15)) * AROW
                              + ks * 32 + (lane >> 4) * 16;
                LDSM4(a_frag[mi], addr);
            }
            #pragma unroll
            for (int p = 0; p < 4; p++) {
                int grp = lane >> 3, w = lane & 7;
                int nsel = p * 2 + (grp >> 1);
                uint32_t addr = sB + (wn + nsel * 8 + w) * AROW
                              + ks * 32 + (grp & 1) * 16;
                uint32_t r[4];
                LDSM4(r, addr);
                b_frag[p * 2][0]     = r[0];
                b_frag[p * 2][1]     = r[1];
                b_frag[p * 2 + 1][0] = r[2];
                b_frag[p * 2 + 1][1] = r[3];
            }
            #pragma unroll
            for (int mi = 0; mi < 2; mi++)
                #pragma unroll
                for (int ni = 0; ni < 8; ni++)
                    MMA16816(acc[mi][ni], a_frag[mi], b_frag[ni]);
        }
    }

    const int g = lane >> 2, tg = lane & 3;
    #pragma unroll
    for (int mi = 0; mi < 2; mi++) {
        int row0 = mBase + wm + mi * 16 + g;
        #pragma unroll
        for (int ni = 0; ni < 8; ni++) {
            int col = nBase + wn + ni * 8 + tg * 2;
            float b0 = __ldg(bias + col), b1 = __ldg(bias + col + 1);
            float2 v0 = make_float2(acc[mi][ni][0] + b0, acc[mi][ni][1] + b1);
            float2 v1 = make_float2(acc[mi][ni][2] + b0, acc[mi][ni][3] + b1);
            *(float2*)(C + (size_t)row0 * N + col) = v0;
            *(float2*)(C + (size_t)(row0 + 8) * N + col) = v1;
        }
    }
}

// ---------------------------------------------------------------------------
// Per-position heads-attention (fp32 exact). Writes bf16 [hi | lo] rows.
// ---------------------------------------------------------------------------
__global__ __launch_bounds__(256) void attn_kernel(
    const float* __restrict__ queries, const float* __restrict__ keys,
    const float* __restrict__ values, const int* __restrict__ mask)
{
    __shared__ float cq[1024];
    __shared__ float kT[64 * 17];
    __shared__ float vv[1024];
    __shared__ float sc[16][16];

    const int pos = blockIdx.x;
    const int n = pos >> 12;
    const int t = pos & (SKV - 1);
    const int tid = threadIdx.x;

    const float* cqrow = (t & 1)
        ? (g_cond  + (size_t)(n * SQ + (t >> 1)) * EDIM)
        : (queries + (size_t)(n * SQ + (t >> 1)) * EDIM);
    const float* krow = keys   + (size_t)pos * EDIM;
    const float* vrow = values + (size_t)pos * EDIM;

    ((float4*)cq)[tid] = ((const float4*)cqrow)[tid];
    ((float4*)vv)[tid] = ((const float4*)vrow)[tid];
    {
        float4 kv = ((const float4*)krow)[tid];
        int gidx = tid * 4;
        #pragma unroll
        for (int i = 0; i < 4; i++) {
            int gg = gidx + i;
            kT[(gg & 63) * 17 + (gg >> 6)] = (&kv.x)[i];
        }
    }
    __syncthreads();

    const int h = tid >> 4;
    const int e = tid & 15;
    float s = 0.f;
    #pragma unroll
    for (int d = 0; d < HDIM; d++)
        s += cq[h * HDIM + d] * kT[d * 17 + e];
    s *= 0.125f;

    if (mask[(size_t)pos * (HEADS * HEADS) + h * 16 + e] == 0) s = -1e20f;
    sc[h][e] = s;
    __syncthreads();

    float mx = -INFINITY;
    #pragma unroll
    for (int j = 0; j < 16; j++) mx = fmaxf(mx, sc[h][j]);
    float denom = 0.f;
    #pragma unroll
    for (int j = 0; j < 16; j++) denom += expf(sc[h][j] - mx);
    float p = expf(s - mx) / denom;
    __syncthreads();
    sc[h][e] = p;
    __syncthreads();

    const int obase = tid * 4;
    const int oh = obase >> 6;
    const int od = obase & 63;
    float a0 = 0.f, a1 = 0.f, a2 = 0.f, a3 = 0.f;
    #pragma unroll
    for (int j = 0; j < 16; j++) {
        float a = sc[oh][j];
        const float* vj = vv + j * HDIM + od;
        a0 += a * vj[0];
        a1 += a * vj[1];
        a2 += a * vj[2];
        a3 += a * vj[3];
    }

    float o[4] = {a0, a1, a2, a3};
    __nv_bfloat16 hi[4], lo[4];
    #pragma unroll
    for (int j = 0; j < 4; j++) {
        hi[j] = __float2bfloat16_rn(o[j]);
        lo[j] = __float2bfloat16_rn(o[j] - __bfloat162float(hi[j]));
    }
    size_t base = (size_t)pos * (2 * EDIM) + obase;
    *(uint2*)(g_aoext + base)        = *(uint2*)hi;
    *(uint2*)(g_aoext + base + EDIM) = *(uint2*)lo;
}

// ---------------------------------------------------------------------------
// Launch
// ---------------------------------------------------------------------------
extern "C" void kernel_launch(void* const* d_in, const int* in_sizes, int n_in,
                              void* d_out, int out_size)
{
    const float* values    = (const float*)d_in[0];
    const float* keys      = (const float*)d_in[1];
    const float* queries   = (const float*)d_in[2];
    const int*   mask      = (const int*)  d_in[3];
    const float* condition = (const float*)d_in[4];
    const float* Wc        = (const float*)d_in[5];
    const float* bc        = (const float*)d_in[6];
    const float* Wo        = (const float*)d_in[7];
    const float* bo        = (const float*)d_in[8];
    float* out = (float*)d_out;

    float* cond_ptr;
    __nv_bfloat16 *cext, *wcext, *woext, *aoext;
    cudaGetSymbolAddress((void**)&cond_ptr, g_cond);
    cudaGetSymbolAddress((void**)&cext,  g_condext);
    cudaGetSymbolAddress((void**)&wcext, g_wcext);
    cudaGetSymbolAddress((void**)&woext, g_woext);
    cudaGetSymbolAddress((void**)&aoext, g_aoext);

    cudaFuncSetAttribute(gemm_hmma,
                         cudaFuncAttributeMaxDynamicSharedMemorySize, DSMEM);

    // splits
    {
        int n = NBATCH * SQ * CDIM;
        split_pack<<<n / 4 / 256, 256>>>(condition, cext, CDIM, n);
        n = EDIM * CDIM;
        split_pack<<<n / 4 / 256, 256>>>(Wc, wcext, CDIM, n);
        n = EDIM * EDIM;
        split_pack<<<n / 4 / 256, 256>>>(Wo, woext, EDIM, n);
    }

    // 1) cond = condition @ Wc^T + bc : M=8192, N=1024, K=512 (K3=1536)
    {
        dim3 grid(EDIM / BN, (NBATCH * SQ) / BM);
        gemm_hmma<<<grid, 256, DSMEM>>>(cext, wcext, bc, cond_ptr,
                                        NBATCH * SQ, EDIM, CDIM);
    }

    // 2) attention -> g_aoext (bf16 [hi|lo])
    attn_kernel<<<NBATCH * SKV, 256>>>(queries, keys, values, mask);

    // 3) out = attout @ Wo^T + bo : M=16384, N=1024, K=1024 (K3=3072)
    {
        dim3 grid(EDIM / BN, (NBATCH * SKV) / BM);
        gemm_hmma<<<grid, 256, DSMEM>>>(aoext, woext, bo, out,
                                        NBATCH * SKV, EDIM, EDIM);
    }
}